// round 15
// baseline (speedup 1.0000x reference)
#include <cuda_runtime.h>
#include <cstdint>

#define NN 256
#define HH 4
#define DD 32
#define SCALE 0.1767766952966369f  /* 1/sqrt(32) */
#define L2E   1.4426950408889634f
#define M0L2E (14.0f * 1.4426950408889634f)

// ---------------- device globals ----------------
// trib2 fragment-coalesced: float idx = (((h*32+(j>>3))*128+(k>>1))*8+(j&7))*2+(k&1)
__device__ __align__(16) float g_trib2[HH * NN * NN];
__device__ __align__(16) float g_M[HH * DD * DD];
__device__ __align__(16) float g_qb[HH * DD];
__device__ __align__(16) float g_u[HH * DD];
__device__ float g_c0[HH];

// ---------------- helpers ----------------
__device__ __forceinline__ float hif(float x) {
    return __uint_as_float(__float_as_uint(x) & 0xFFFFE000u);
}
__device__ __forceinline__ float lof(float x, float h) {
    return __uint_as_float(__float_as_uint(x - h) & 0xFFFFE000u);
}
__device__ __forceinline__ float rnaf(float x) {
    uint32_t r; asm("cvt.rna.tf32.f32 %0, %1;" : "=r"(r) : "f"(x));
    return __uint_as_float(r);
}
__device__ __forceinline__ float ex2(float x) {
    float r; asm("ex2.approx.ftz.f32 %0, %1;" : "=f"(r) : "f"(x)); return r;
}
__device__ __forceinline__ void mma8(float* d, const uint32_t* a, uint32_t b0, uint32_t b1) {
    asm volatile("mma.sync.aligned.m16n8k8.row.col.f32.tf32.tf32.f32 "
        "{%0,%1,%2,%3},{%4,%5,%6,%7},{%8,%9},{%0,%1,%2,%3};"
        : "+f"(d[0]), "+f"(d[1]), "+f"(d[2]), "+f"(d[3])
        : "r"(a[0]), "r"(a[1]), "r"(a[2]), "r"(a[3]), "r"(b0), "r"(b1));
}
#define U(x) __float_as_uint(x)

// ---------------------------------------------------------------------------
// prep + trib fused (unchanged)
// ---------------------------------------------------------------------------
__global__ void __launch_bounds__(256) prep_trib_kernel(
        const float* __restrict__ x,  const float* __restrict__ Wb,
        const float* __restrict__ bb, const float* __restrict__ Wq,
        const float* __restrict__ bq, const float* __restrict__ Wk,
        const float* __restrict__ bk) {
    int t = threadIdx.x;
    if (blockIdx.x < NN) {
        int jj = blockIdx.x, k = t;
        const float4* xr = reinterpret_cast<const float4*>(x + ((size_t)jj * NN + k) * DD);
        float4 xv[8];
#pragma unroll
        for (int q = 0; q < 8; q++) xv[q] = xr[q];
#pragma unroll
        for (int h = 0; h < HH; h++) {
            const float4* wr = reinterpret_cast<const float4*>(Wb + h * DD);
            float s = bb[h];
#pragma unroll
            for (int q = 0; q < 8; q++) {
                float4 ww = wr[q];
                s += xv[q].x * ww.x + xv[q].y * ww.y + xv[q].z * ww.z + xv[q].w * ww.w;
            }
            int idx = (((h * 32 + (jj >> 3)) * 128 + (k >> 1)) * 8 + (jj & 7)) * 2 + (k & 1);
            g_trib2[idx] = s * L2E;
        }
    } else {
        int h = blockIdx.x - NN;
        int d = t & 31, y = t >> 5;
#pragma unroll
        for (int cc = 0; cc < 4; cc++) {
            int c = y * 4 + cc;
            float s = 0.f;
#pragma unroll
            for (int r = 0; r < DD; r++)
                s += Wq[(h * DD + r) * DD + c] * Wk[(h * DD + r) * DD + d];
            g_M[(h * DD + c) * DD + d] = s * SCALE;
        }
        if (y == 0) {
            float s2 = 0.f, s3 = 0.f;
#pragma unroll
            for (int r = 0; r < DD; r++) {
                s2 += bq[h * DD + r] * Wk[(h * DD + r) * DD + d];
                s3 += Wq[(h * DD + r) * DD + d] * bk[h * DD + r];
            }
            g_qb[h * DD + d] = s2 * SCALE;
            g_u[h * DD + d]  = s3 * SCALE;
            if (d == 0) {
                float s4 = 0.f;
#pragma unroll
                for (int r = 0; r < DD; r++) s4 += bq[h * DD + r] * bk[h * DD + r];
                g_c0[h] = s4 * SCALE;
            }
        }
    }
}

// ---------------------------------------------------------------------------
// Fused attention: CTA=(i,h), 256 threads / 8 warps, warp = 32 query rows.
// Sigma-permutation structure (R13), main loop MANUALLY ROTATED:
//   softmax(b) -> [trib(b+1) + MMA1(b+1)] -> MMA2(b)
// so cross-block independent work covers MUFU/LDS/L2/tensor latency.
// No staging; NO shared-memory writes and NO syncs in the main loop.
// ---------------------------------------------------------------------------
#define XB_OFF 0
#define XT_OFF 36864           /* 256*36*4 */
#define DYN_BYTES 70144        /* + 32*260*4 = 33280 */

extern __shared__ char dynsm[];

__global__ void __launch_bounds__(256, 1) attn_kernel(
        const float* __restrict__ x, const float* __restrict__ mask,
        const float* __restrict__ Wv, const float* __restrict__ bv,
        float* __restrict__ out) {
    const int i = blockIdx.x, h = blockIdx.y;
    const int t = threadIdx.x;
    const int w = t >> 5, lane = t & 31, g = lane >> 2, tc = lane & 3;
    const int R = w * 32;

    float*  xbw = reinterpret_cast<float*>(dynsm + XB_OFF);
    float4* xb4 = reinterpret_cast<float4*>(dynsm + XB_OFF);
    float*  xtf = reinterpret_cast<float*>(dynsm + XT_OFF);
    float4* xt4 = reinterpret_cast<float4*>(dynsm + XT_OFF);

    __shared__ __align__(16) float4 MB4s[DD * 20];
    __shared__ __align__(8)  float Wvh[DD * 36], Wvl[DD * 36];
    __shared__ __align__(8)  float mbsm[NN];
    __shared__ float basej[NN];
    __shared__ __align__(8)  float qbs[DD], bvs[DD];

    // ================= prologue (all 256 threads) =================
    {
        const int j = t;
        float xv[DD], xr[DD];
        const float4* xg = reinterpret_cast<const float4*>(x + ((size_t)i * NN + j) * DD);
#pragma unroll
        for (int q = 0; q < 8; q++) {
            float4 v = xg[q];
            xv[4*q] = v.x; xv[4*q+1] = v.y; xv[4*q+2] = v.z; xv[4*q+3] = v.w;
        }
#pragma unroll
        for (int d = 0; d < DD; d++) xr[d] = rnaf(xv[d]);

        // XB (sigma d-order)
#pragma unroll
        for (int tcc = 0; tcc < 4; tcc++)
#pragma unroll
            for (int kt2 = 0; kt2 < 2; kt2++)
                xb4[j * 9 + tcc * 2 + kt2] = make_float4(
                    xr[16*kt2 + 2*tcc], xr[16*kt2 + 2*tcc + 1],
                    xr[16*kt2 + 8 + 2*tcc], xr[16*kt2 + 8 + 2*tcc + 1]);
        // XT (sigma key-order)
        {
            int blk = j >> 5, m = j & 31, kt = m >> 3, mm = m & 7;
            int word = blk * 32 + (mm >> 1) * 8 + kt * 2 + (mm & 1);
#pragma unroll
            for (int d = 0; d < DD; d++)
                xtf[d * 260 + word] = xr[d];
        }
        mbsm[j] = (mask[i * NN + j] - 1.0f) * 1e9f * L2E;
        float cbv = g_c0[h];
#pragma unroll
        for (int c = 0; c < DD; c++) cbv += xv[c] * g_u[h * DD + c];
        basej[j] = cbv * L2E - M0L2E;

        // MB4s (M hi/lo pairs)
#pragma unroll
        for (int q = 0; q < 2; q++) {
            int ee = t + q * 256;
            int d = ee >> 4, r = ee & 15, kt = r >> 2, cc = r & 3;
            int k0 = kt * 8 + cc;
            float m0 = g_M[((size_t)h * DD + k0) * DD + d];
            float m1 = g_M[((size_t)h * DD + k0 + 4) * DD + d];
            float h0 = hif(m0), h1 = hif(m1);
            MB4s[d * 20 + kt * 4 + cc] = make_float4(h0, lof(m0, h0), h1, lof(m1, h1));
        }
        // Wv hi/lo
#pragma unroll
        for (int q = 0; q < 4; q++) {
            int ee = t + q * 256;
            int r = ee >> 5, c = ee & 31;
            float wv = Wv[((size_t)h * DD + r) * DD + c];
            float hh = hif(wv);
            Wvh[r * 36 + c] = hh;
            Wvl[r * 36 + c] = lof(wv, hh);
        }
        if (t < DD) qbs[t] = g_qb[h * DD + t];
        else if (t < 2 * DD) bvs[t - DD] = bv[h * DD + (t - DD)];
    }
    __syncthreads();

    // ========= Q~ = X M + qb for both m-tiles (B = Mh/Ml 2-pass) =====
    uint32_t qf0[16], qf1[16];
    {
        float qt0[16], qt1[16];
#pragma unroll
        for (int q = 0; q < 16; q++) { qt0[q] = 0.f; qt1[q] = 0.f; }
#pragma unroll
        for (int kt = 0; kt < 4; kt++) {
            int w0 = (tc >> 1) * 8 + kt * 2 + (tc & 1);
            uint32_t a0[4] = {U(xbw[(R + g     ) * 36 + w0]),      U(xbw[(R + g + 8 ) * 36 + w0]),
                              U(xbw[(R + g     ) * 36 + w0 + 16]), U(xbw[(R + g + 8 ) * 36 + w0 + 16])};
            uint32_t a1[4] = {U(xbw[(R + g + 16) * 36 + w0]),      U(xbw[(R + g + 24) * 36 + w0]),
                              U(xbw[(R + g + 16) * 36 + w0 + 16]), U(xbw[(R + g + 24) * 36 + w0 + 16])};
#pragma unroll
            for (int nt = 0; nt < 4; nt++) {
                float4 bm = MB4s[(nt * 8 + g) * 20 + kt * 4 + tc];
                mma8(&qt0[nt*4], a0, U(bm.x), U(bm.z));
                mma8(&qt0[nt*4], a0, U(bm.y), U(bm.w));
                mma8(&qt1[nt*4], a1, U(bm.x), U(bm.z));
                mma8(&qt1[nt*4], a1, U(bm.y), U(bm.w));
            }
        }
#pragma unroll
        for (int kt = 0; kt < 4; kt++) {
            float2 qb2 = *reinterpret_cast<const float2*>(&qbs[kt * 8 + 2 * tc]);
            qf0[kt*4+0] = U(rnaf(qt0[kt*4+0] + qb2.x));
            qf0[kt*4+1] = U(rnaf(qt0[kt*4+2] + qb2.x));
            qf0[kt*4+2] = U(rnaf(qt0[kt*4+1] + qb2.y));
            qf0[kt*4+3] = U(rnaf(qt0[kt*4+3] + qb2.y));
            qf1[kt*4+0] = U(rnaf(qt1[kt*4+0] + qb2.x));
            qf1[kt*4+1] = U(rnaf(qt1[kt*4+2] + qb2.x));
            qf1[kt*4+2] = U(rnaf(qt1[kt*4+1] + qb2.y));
            qf1[kt*4+3] = U(rnaf(qt1[kt*4+3] + qb2.y));
        }
    }
    const float base0 = basej[R + g],      base1 = basej[R + g + 8];
    const float base2 = basej[R + g + 16], base3 = basej[R + g + 24];

    float o0[16], o1[16];
#pragma unroll
    for (int q = 0; q < 16; q++) { o0[q] = 0.f; o1[q] = 0.f; }
    float l0 = 0.f, l1 = 0.f, l2 = 0.f, l3 = 0.f;

    const float2* tpb = reinterpret_cast<const float2*>(g_trib2);
    const int jg = h * 32 + (R >> 3);

    // ============== rotated main loop: 8 key-blocks of 32, NO syncs ==============
    float2 tb[16];
    float s0[16], s1[16];

    // pipeline prologue: trib(0) + MMA1(0)
#pragma unroll
    for (int m = 0; m < 4; m++)
#pragma unroll
        for (int nt = 0; nt < 4; nt++)
            tb[m*4+nt] = tpb[((jg + m) << 10) + ((nt * 4 + tc) * 8 + g)];
#pragma unroll
    for (int q = 0; q < 16; q++) { s0[q] = 0.f; s1[q] = 0.f; }
#pragma unroll
    for (int nt = 0; nt < 4; nt++) {
        float4 ba  = xb4[(nt*8 + g) * 9 + tc * 2];
        float4 bb2 = xb4[(nt*8 + g) * 9 + tc * 2 + 1];
        mma8(&s0[nt*4], &qf0[0],  U(ba.x),  U(ba.y));
        mma8(&s0[nt*4], &qf0[4],  U(ba.z),  U(ba.w));
        mma8(&s0[nt*4], &qf0[8],  U(bb2.x), U(bb2.y));
        mma8(&s0[nt*4], &qf0[12], U(bb2.z), U(bb2.w));
        mma8(&s1[nt*4], &qf1[0],  U(ba.x),  U(ba.y));
        mma8(&s1[nt*4], &qf1[4],  U(ba.z),  U(ba.w));
        mma8(&s1[nt*4], &qf1[8],  U(bb2.x), U(bb2.y));
        mma8(&s1[nt*4], &qf1[12], U(bb2.z), U(bb2.w));
    }

#pragma unroll 1
    for (int b = 0; b < 8; b++) {
        const int kb = b * 32;

        // ---- softmax(b) in registers; pa = A fragments (sigma renaming) ----
        uint32_t pa0[16], pa1[16];
#pragma unroll
        for (int nt = 0; nt < 4; nt++) {
            float2 mv = *reinterpret_cast<const float2*>(&mbsm[kb + nt*8 + 2*tc]);
            float p00 = rnaf(ex2(fmaf(s0[nt*4+0], L2E, base0 + mv.x + tb[nt].x)));
            float p01 = rnaf(ex2(fmaf(s0[nt*4+1], L2E, base0 + mv.y + tb[nt].y)));
            float p02 = rnaf(ex2(fmaf(s0[nt*4+2], L2E, base1 + mv.x + tb[4+nt].x)));
            float p03 = rnaf(ex2(fmaf(s0[nt*4+3], L2E, base1 + mv.y + tb[4+nt].y)));
            float p10 = rnaf(ex2(fmaf(s1[nt*4+0], L2E, base2 + mv.x + tb[8+nt].x)));
            float p11 = rnaf(ex2(fmaf(s1[nt*4+1], L2E, base2 + mv.y + tb[8+nt].y)));
            float p12 = rnaf(ex2(fmaf(s1[nt*4+2], L2E, base3 + mv.x + tb[12+nt].x)));
            float p13 = rnaf(ex2(fmaf(s1[nt*4+3], L2E, base3 + mv.y + tb[12+nt].y)));
            l0 += p00 + p01; l1 += p02 + p03;
            l2 += p10 + p11; l3 += p12 + p13;
            pa0[nt*4+0] = U(p00); pa0[nt*4+1] = U(p02);
            pa0[nt*4+2] = U(p01); pa0[nt*4+3] = U(p03);
            pa1[nt*4+0] = U(p10); pa1[nt*4+1] = U(p12);
            pa1[nt*4+2] = U(p11); pa1[nt*4+3] = U(p13);
        }

        // ---- pipeline: trib(b+1) + MMA1(b+1) (independent of pa/o) ----
        float ns0[16], ns1[16];
        float2 ntb[16];
        if (b < 7) {
            const int kn = kb + 32;
#pragma unroll
            for (int m = 0; m < 4; m++)
#pragma unroll
                for (int nt = 0; nt < 4; nt++)
                    ntb[m*4+nt] = tpb[((jg + m) << 10) + (kn * 4 + (nt * 4 + tc) * 8 + g)];
#pragma unroll
            for (int q = 0; q < 16; q++) { ns0[q] = 0.f; ns1[q] = 0.f; }
#pragma unroll
            for (int nt = 0; nt < 4; nt++) {
                float4 ba  = xb4[(kn + nt*8 + g) * 9 + tc * 2];
                float4 bb2 = xb4[(kn + nt*8 + g) * 9 + tc * 2 + 1];
                mma8(&ns0[nt*4], &qf0[0],  U(ba.x),  U(ba.y));
                mma8(&ns0[nt*4], &qf0[4],  U(ba.z),  U(ba.w));
                mma8(&ns0[nt*4], &qf0[8],  U(bb2.x), U(bb2.y));
                mma8(&ns0[nt*4], &qf0[12], U(bb2.z), U(bb2.w));
                mma8(&ns1[nt*4], &qf1[0],  U(ba.x),  U(ba.y));
                mma8(&ns1[nt*4], &qf1[4],  U(ba.z),  U(ba.w));
                mma8(&ns1[nt*4], &qf1[8],  U(bb2.x), U(bb2.y));
                mma8(&ns1[nt*4], &qf1[12], U(bb2.z), U(bb2.w));
            }
        }

        // ---- MMA2(b): O += P X, B shared across both m-tiles ----
#pragma unroll
        for (int nt = 0; nt < 4; nt++) {
            float4 ba  = xt4[(nt*8 + g) * 65 + (kb >> 5) * 8 + tc * 2];
            float4 bb2 = xt4[(nt*8 + g) * 65 + (kb >> 5) * 8 + tc * 2 + 1];
            mma8(&o0[nt*4], &pa0[0],  U(ba.x),  U(ba.y));
            mma8(&o0[nt*4], &pa0[4],  U(ba.z),  U(ba.w));
            mma8(&o0[nt*4], &pa0[8],  U(bb2.x), U(bb2.y));
            mma8(&o0[nt*4], &pa0[12], U(bb2.z), U(bb2.w));
            mma8(&o1[nt*4], &pa1[0],  U(ba.x),  U(ba.y));
            mma8(&o1[nt*4], &pa1[4],  U(ba.z),  U(ba.w));
            mma8(&o1[nt*4], &pa1[8],  U(bb2.x), U(bb2.y));
            mma8(&o1[nt*4], &pa1[12], U(bb2.z), U(bb2.w));
        }

        if (b < 7) {
#pragma unroll
            for (int q = 0; q < 16; q++) { s0[q] = ns0[q]; s1[q] = ns1[q]; }
#pragma unroll
            for (int q = 0; q < 16; q++) tb[q] = ntb[q];
        }
    }

    // ===== epilogue: F = (O Wv^T)/l + bv, A = O regs (sigma), 3xTF32 =====
    float f0[16], f1[16];
#pragma unroll
    for (int q = 0; q < 16; q++) { f0[q] = 0.f; f1[q] = 0.f; }
#pragma unroll
    for (int kt = 0; kt < 4; kt++) {
        float v00 = o0[kt*4+0], v01 = o0[kt*4+2], v02 = o0[kt*4+1], v03 = o0[kt*4+3];
        float v10 = o1[kt*4+0], v11 = o1[kt*4+2], v12 = o1[kt*4+1], v13 = o1[kt*4+3];
        uint32_t oh0[4] = {U(hif(v00)), U(hif(v01)), U(hif(v02)), U(hif(v03))};
        uint32_t ol0[4] = {U(lof(v00, hif(v00))), U(lof(v01, hif(v01))),
                           U(lof(v02, hif(v02))), U(lof(v03, hif(v03)))};
        uint32_t oh1[4] = {U(hif(v10)), U(hif(v11)), U(hif(v12)), U(hif(v13))};
        uint32_t ol1[4] = {U(lof(v10, hif(v10))), U(lof(v11, hif(v11))),
                           U(lof(v12, hif(v12))), U(lof(v13, hif(v13)))};
#pragma unroll
        for (int nt = 0; nt < 4; nt++) {
            float2 bh = *reinterpret_cast<const float2*>(&Wvh[(nt*8 + g) * 36 + kt*8 + 2*tc]);
            float2 bl = *reinterpret_cast<const float2*>(&Wvl[(nt*8 + g) * 36 + kt*8 + 2*tc]);
            mma8(&f0[nt*4], oh0, U(bh.x), U(bh.y));
            mma8(&f0[nt*4], oh0, U(bl.x), U(bl.y));
            mma8(&f0[nt*4], ol0, U(bh.x), U(bh.y));
            mma8(&f1[nt*4], oh1, U(bh.x), U(bh.y));
            mma8(&f1[nt*4], oh1, U(bl.x), U(bl.y));
            mma8(&f1[nt*4], ol1, U(bh.x), U(bh.y));
        }
    }

    l0 += __shfl_xor_sync(0xFFFFFFFFu, l0, 1); l0 += __shfl_xor_sync(0xFFFFFFFFu, l0, 2);
    l1 += __shfl_xor_sync(0xFFFFFFFFu, l1, 1); l1 += __shfl_xor_sync(0xFFFFFFFFu, l1, 2);
    l2 += __shfl_xor_sync(0xFFFFFFFFu, l2, 1); l2 += __shfl_xor_sync(0xFFFFFFFFu, l2, 2);
    l3 += __shfl_xor_sync(0xFFFFFFFFu, l3, 1); l3 += __shfl_xor_sync(0xFFFFFFFFu, l3, 2);
    float inv0 = 1.f / l0, inv1 = 1.f / l1, inv2 = 1.f / l2, inv3 = 1.f / l3;

#pragma unroll
    for (int nt = 0; nt < 4; nt++) {
        int c0 = nt * 8 + 2 * tc;
        float2 bb2 = *reinterpret_cast<const float2*>(&bvs[c0]);
        float2 v0 = make_float2(f0[nt*4+0] * inv0 + bb2.x, f0[nt*4+1] * inv0 + bb2.y);
        float2 v1 = make_float2(f0[nt*4+2] * inv1 + bb2.x, f0[nt*4+3] * inv1 + bb2.y);
        float2 v2 = make_float2(f1[nt*4+0] * inv2 + bb2.x, f1[nt*4+1] * inv2 + bb2.y);
        float2 v3 = make_float2(f1[nt*4+2] * inv3 + bb2.x, f1[nt*4+3] * inv3 + bb2.y);
        *reinterpret_cast<float2*>(out + (((size_t)i * NN + R + g     ) * HH + h) * DD + c0) = v0;
        *reinterpret_cast<float2*>(out + (((size_t)i * NN + R + g + 8 ) * HH + h) * DD + c0) = v1;
        *reinterpret_cast<float2*>(out + (((size_t)i * NN + R + g + 16) * HH + h) * DD + c0) = v2;
        *reinterpret_cast<float2*>(out + (((size_t)i * NN + R + g + 24) * HH + h) * DD + c0) = v3;
    }
}

// ---------------------------------------------------------------------------
extern "C" void kernel_launch(void* const* d_in, const int* in_sizes, int n_in,
                              void* d_out, int out_size) {
    const float* x    = (const float*)d_in[0];
    const float* mask = (const float*)d_in[1];
    const float* Wq   = (const float*)d_in[2];
    const float* bq   = (const float*)d_in[3];
    const float* Wk   = (const float*)d_in[4];
    const float* bk   = (const float*)d_in[5];
    const float* Wv   = (const float*)d_in[6];
    const float* bv   = (const float*)d_in[7];
    const float* Wb   = (const float*)d_in[8];
    const float* bb   = (const float*)d_in[9];
    float* out = (float*)d_out;

    cudaFuncSetAttribute(attn_kernel, cudaFuncAttributeMaxDynamicSharedMemorySize, DYN_BYTES);

    prep_trib_kernel<<<NN + HH, 256>>>(x, Wb, bb, Wq, bq, Wk, bk);
    attn_kernel<<<dim3(NN, HH), 256, DYN_BYTES>>>(x, mask, Wv, bv, out);
}

// round 16
// speedup vs baseline: 1.0900x; 1.0900x over previous
#include <cuda_runtime.h>
#include <cstdint>

#define NN 256
#define HH 4
#define DD 32
#define SCALE 0.1767766952966369f  /* 1/sqrt(32) */
#define L2E   1.4426950408889634f
#define M0L2E (14.0f * 1.4426950408889634f)

// ---------------- device globals ----------------
// trib2 fragment-coalesced: float idx = (((h*32+(j>>3))*128+(k>>1))*8+(j&7))*2+(k&1)
__device__ __align__(16) float g_trib2[HH * NN * NN];
__device__ __align__(16) float g_M[HH * DD * DD];
__device__ __align__(16) float g_qb[HH * DD];
__device__ __align__(16) float g_u[HH * DD];
__device__ float g_c0[HH];

// ---------------- helpers ----------------
__device__ __forceinline__ float hif(float x) {
    return __uint_as_float(__float_as_uint(x) & 0xFFFFE000u);
}
__device__ __forceinline__ float lof(float x, float h) {
    return __uint_as_float(__float_as_uint(x - h) & 0xFFFFE000u);
}
__device__ __forceinline__ float rnaf(float x) {
    uint32_t r; asm("cvt.rna.tf32.f32 %0, %1;" : "=r"(r) : "f"(x));
    return __uint_as_float(r);
}
__device__ __forceinline__ float ex2(float x) {
    float r; asm("ex2.approx.ftz.f32 %0, %1;" : "=f"(r) : "f"(x)); return r;
}
__device__ __forceinline__ void mma8(float* d, const uint32_t* a, uint32_t b0, uint32_t b1) {
    asm volatile("mma.sync.aligned.m16n8k8.row.col.f32.tf32.tf32.f32 "
        "{%0,%1,%2,%3},{%4,%5,%6,%7},{%8,%9},{%0,%1,%2,%3};"
        : "+f"(d[0]), "+f"(d[1]), "+f"(d[2]), "+f"(d[3])
        : "r"(a[0]), "r"(a[1]), "r"(a[2]), "r"(a[3]), "r"(b0), "r"(b1));
}
#define U(x) __float_as_uint(x)

// ---------------------------------------------------------------------------
// prep + trib fused (unchanged)
// ---------------------------------------------------------------------------
__global__ void __launch_bounds__(256) prep_trib_kernel(
        const float* __restrict__ x,  const float* __restrict__ Wb,
        const float* __restrict__ bb, const float* __restrict__ Wq,
        const float* __restrict__ bq, const float* __restrict__ Wk,
        const float* __restrict__ bk) {
    int t = threadIdx.x;
    if (blockIdx.x < NN) {
        int jj = blockIdx.x, k = t;
        const float4* xr = reinterpret_cast<const float4*>(x + ((size_t)jj * NN + k) * DD);
        float4 xv[8];
#pragma unroll
        for (int q = 0; q < 8; q++) xv[q] = xr[q];
#pragma unroll
        for (int h = 0; h < HH; h++) {
            const float4* wr = reinterpret_cast<const float4*>(Wb + h * DD);
            float s = bb[h];
#pragma unroll
            for (int q = 0; q < 8; q++) {
                float4 ww = wr[q];
                s += xv[q].x * ww.x + xv[q].y * ww.y + xv[q].z * ww.z + xv[q].w * ww.w;
            }
            int idx = (((h * 32 + (jj >> 3)) * 128 + (k >> 1)) * 8 + (jj & 7)) * 2 + (k & 1);
            g_trib2[idx] = s * L2E;
        }
    } else {
        int h = blockIdx.x - NN;
        int d = t & 31, y = t >> 5;
#pragma unroll
        for (int cc = 0; cc < 4; cc++) {
            int c = y * 4 + cc;
            float s = 0.f;
#pragma unroll
            for (int r = 0; r < DD; r++)
                s += Wq[(h * DD + r) * DD + c] * Wk[(h * DD + r) * DD + d];
            g_M[(h * DD + c) * DD + d] = s * SCALE;
        }
        if (y == 0) {
            float s2 = 0.f, s3 = 0.f;
#pragma unroll
            for (int r = 0; r < DD; r++) {
                s2 += bq[h * DD + r] * Wk[(h * DD + r) * DD + d];
                s3 += Wq[(h * DD + r) * DD + d] * bk[h * DD + r];
            }
            g_qb[h * DD + d] = s2 * SCALE;
            g_u[h * DD + d]  = s3 * SCALE;
            if (d == 0) {
                float s4 = 0.f;
#pragma unroll
                for (int r = 0; r < DD; r++) s4 += bq[h * DD + r] * bk[h * DD + r];
                g_c0[h] = s4 * SCALE;
            }
        }
    }
}

// ---------------------------------------------------------------------------
// Fused attention: CTA=(i,h), 256 threads / 8 warps, warp = 32 query rows.
// R13 sigma structure, register-dieted to <=128 regs so TWO CTAs fit per SM
// (4 warps/SMSP hides the latency that single-warp ILP could not).
// trib is loaded inline in the softmax loop (no tb register array).
// ---------------------------------------------------------------------------
#define XB_OFF 0
#define XT_OFF 36864           /* 256*36*4 */
#define DYN_BYTES 70144        /* + 32*260*4 = 33280 */

extern __shared__ char dynsm[];

__global__ void __launch_bounds__(256, 2) attn_kernel(
        const float* __restrict__ x, const float* __restrict__ mask,
        const float* __restrict__ Wv, const float* __restrict__ bv,
        float* __restrict__ out) {
    const int i = blockIdx.x, h = blockIdx.y;
    const int t = threadIdx.x;
    const int w = t >> 5, lane = t & 31, g = lane >> 2, tc = lane & 3;
    const int R = w * 32;

    float*  xbw = reinterpret_cast<float*>(dynsm + XB_OFF);
    float4* xb4 = reinterpret_cast<float4*>(dynsm + XB_OFF);
    float*  xtf = reinterpret_cast<float*>(dynsm + XT_OFF);
    float4* xt4 = reinterpret_cast<float4*>(dynsm + XT_OFF);

    __shared__ __align__(16) float4 MB4s[DD * 20];
    __shared__ __align__(8)  float Wvh[DD * 36], Wvl[DD * 36];
    __shared__ __align__(8)  float mbsm[NN];
    __shared__ float basej[NN];
    __shared__ __align__(8)  float qbs[DD], bvs[DD];

    // ================= prologue (all 256 threads) =================
    {
        const int j = t;
        float xv[DD], xr[DD];
        const float4* xg = reinterpret_cast<const float4*>(x + ((size_t)i * NN + j) * DD);
#pragma unroll
        for (int q = 0; q < 8; q++) {
            float4 v = xg[q];
            xv[4*q] = v.x; xv[4*q+1] = v.y; xv[4*q+2] = v.z; xv[4*q+3] = v.w;
        }
#pragma unroll
        for (int d = 0; d < DD; d++) xr[d] = rnaf(xv[d]);

        // XB (sigma d-order)
#pragma unroll
        for (int tcc = 0; tcc < 4; tcc++)
#pragma unroll
            for (int kt2 = 0; kt2 < 2; kt2++)
                xb4[j * 9 + tcc * 2 + kt2] = make_float4(
                    xr[16*kt2 + 2*tcc], xr[16*kt2 + 2*tcc + 1],
                    xr[16*kt2 + 8 + 2*tcc], xr[16*kt2 + 8 + 2*tcc + 1]);
        // XT (sigma key-order)
        {
            int blk = j >> 5, m = j & 31, kt = m >> 3, mm = m & 7;
            int word = blk * 32 + (mm >> 1) * 8 + kt * 2 + (mm & 1);
#pragma unroll
            for (int d = 0; d < DD; d++)
                xtf[d * 260 + word] = xr[d];
        }
        mbsm[j] = (mask[i * NN + j] - 1.0f) * 1e9f * L2E;
        float cbv = g_c0[h];
#pragma unroll
        for (int c = 0; c < DD; c++) cbv += xv[c] * g_u[h * DD + c];
        basej[j] = cbv * L2E - M0L2E;

        // MB4s (M hi/lo pairs)
#pragma unroll
        for (int q = 0; q < 2; q++) {
            int ee = t + q * 256;
            int d = ee >> 4, r = ee & 15, kt = r >> 2, cc = r & 3;
            int k0 = kt * 8 + cc;
            float m0 = g_M[((size_t)h * DD + k0) * DD + d];
            float m1 = g_M[((size_t)h * DD + k0 + 4) * DD + d];
            float h0 = hif(m0), h1 = hif(m1);
            MB4s[d * 20 + kt * 4 + cc] = make_float4(h0, lof(m0, h0), h1, lof(m1, h1));
        }
        // Wv hi/lo
#pragma unroll
        for (int q = 0; q < 4; q++) {
            int ee = t + q * 256;
            int r = ee >> 5, c = ee & 31;
            float wv = Wv[((size_t)h * DD + r) * DD + c];
            float hh = hif(wv);
            Wvh[r * 36 + c] = hh;
            Wvl[r * 36 + c] = lof(wv, hh);
        }
        if (t < DD) qbs[t] = g_qb[h * DD + t];
        else if (t < 2 * DD) bvs[t - DD] = bv[h * DD + (t - DD)];
    }
    __syncthreads();

    // ========= Q~ = X M + qb for both m-tiles (B = Mh/Ml 2-pass) =====
    uint32_t qf0[16], qf1[16];
    {
        float qt0[16], qt1[16];
#pragma unroll
        for (int q = 0; q < 16; q++) { qt0[q] = 0.f; qt1[q] = 0.f; }
#pragma unroll
        for (int kt = 0; kt < 4; kt++) {
            int w0 = (tc >> 1) * 8 + kt * 2 + (tc & 1);
            uint32_t a0[4] = {U(xbw[(R + g     ) * 36 + w0]),      U(xbw[(R + g + 8 ) * 36 + w0]),
                              U(xbw[(R + g     ) * 36 + w0 + 16]), U(xbw[(R + g + 8 ) * 36 + w0 + 16])};
            uint32_t a1[4] = {U(xbw[(R + g + 16) * 36 + w0]),      U(xbw[(R + g + 24) * 36 + w0]),
                              U(xbw[(R + g + 16) * 36 + w0 + 16]), U(xbw[(R + g + 24) * 36 + w0 + 16])};
#pragma unroll
            for (int nt = 0; nt < 4; nt++) {
                float4 bm = MB4s[(nt * 8 + g) * 20 + kt * 4 + tc];
                mma8(&qt0[nt*4], a0, U(bm.x), U(bm.z));
                mma8(&qt0[nt*4], a0, U(bm.y), U(bm.w));
                mma8(&qt1[nt*4], a1, U(bm.x), U(bm.z));
                mma8(&qt1[nt*4], a1, U(bm.y), U(bm.w));
            }
        }
#pragma unroll
        for (int kt = 0; kt < 4; kt++) {
            float2 qb2 = *reinterpret_cast<const float2*>(&qbs[kt * 8 + 2 * tc]);
            qf0[kt*4+0] = U(rnaf(qt0[kt*4+0] + qb2.x));
            qf0[kt*4+1] = U(rnaf(qt0[kt*4+2] + qb2.x));
            qf0[kt*4+2] = U(rnaf(qt0[kt*4+1] + qb2.y));
            qf0[kt*4+3] = U(rnaf(qt0[kt*4+3] + qb2.y));
            qf1[kt*4+0] = U(rnaf(qt1[kt*4+0] + qb2.x));
            qf1[kt*4+1] = U(rnaf(qt1[kt*4+2] + qb2.x));
            qf1[kt*4+2] = U(rnaf(qt1[kt*4+1] + qb2.y));
            qf1[kt*4+3] = U(rnaf(qt1[kt*4+3] + qb2.y));
        }
    }
    const float base0 = basej[R + g],      base1 = basej[R + g + 8];
    const float base2 = basej[R + g + 16], base3 = basej[R + g + 24];

    float o0[16], o1[16];
#pragma unroll
    for (int q = 0; q < 16; q++) { o0[q] = 0.f; o1[q] = 0.f; }
    float l0 = 0.f, l1 = 0.f, l2 = 0.f, l3 = 0.f;

    const float2* tpb = reinterpret_cast<const float2*>(g_trib2);
    const int jg = h * 32 + (R >> 3);

    // ================= main loop: 8 key-blocks of 32, NO syncs =================
#pragma unroll 1
    for (int kb = 0; kb < NN; kb += 32) {
        // ---- MMA1: S = Q~ X^T, B shared across both m-tiles ----
        float s0[16], s1[16];
#pragma unroll
        for (int q = 0; q < 16; q++) { s0[q] = 0.f; s1[q] = 0.f; }
#pragma unroll
        for (int nt = 0; nt < 4; nt++) {
            float4 ba  = xb4[(kb + nt*8 + g) * 9 + tc * 2];
            float4 bb2 = xb4[(kb + nt*8 + g) * 9 + tc * 2 + 1];
            mma8(&s0[nt*4], &qf0[0],  U(ba.x),  U(ba.y));
            mma8(&s0[nt*4], &qf0[4],  U(ba.z),  U(ba.w));
            mma8(&s0[nt*4], &qf0[8],  U(bb2.x), U(bb2.y));
            mma8(&s0[nt*4], &qf0[12], U(bb2.z), U(bb2.w));
            mma8(&s1[nt*4], &qf1[0],  U(ba.x),  U(ba.y));
            mma8(&s1[nt*4], &qf1[4],  U(ba.z),  U(ba.w));
            mma8(&s1[nt*4], &qf1[8],  U(bb2.x), U(bb2.y));
            mma8(&s1[nt*4], &qf1[12], U(bb2.z), U(bb2.w));
        }

        // ---- softmax in registers; trib loaded inline (no live array) ----
        float p0[16], p1[16];
#pragma unroll
        for (int nt = 0; nt < 4; nt++) {
            int toff = kb * 4 + (nt * 4 + tc) * 8 + g;
            float2 mv = *reinterpret_cast<const float2*>(&mbsm[kb + nt*8 + 2*tc]);
            float2 t0 = tpb[((jg + 0) << 10) + toff];
            float2 t1 = tpb[((jg + 1) << 10) + toff];
            float2 t2 = tpb[((jg + 2) << 10) + toff];
            float2 t3 = tpb[((jg + 3) << 10) + toff];
            p0[nt*4+0] = rnaf(ex2(fmaf(s0[nt*4+0], L2E, base0 + mv.x + t0.x)));
            p0[nt*4+1] = rnaf(ex2(fmaf(s0[nt*4+1], L2E, base0 + mv.y + t0.y)));
            p0[nt*4+2] = rnaf(ex2(fmaf(s0[nt*4+2], L2E, base1 + mv.x + t1.x)));
            p0[nt*4+3] = rnaf(ex2(fmaf(s0[nt*4+3], L2E, base1 + mv.y + t1.y)));
            p1[nt*4+0] = rnaf(ex2(fmaf(s1[nt*4+0], L2E, base2 + mv.x + t2.x)));
            p1[nt*4+1] = rnaf(ex2(fmaf(s1[nt*4+1], L2E, base2 + mv.y + t2.y)));
            p1[nt*4+2] = rnaf(ex2(fmaf(s1[nt*4+2], L2E, base3 + mv.x + t3.x)));
            p1[nt*4+3] = rnaf(ex2(fmaf(s1[nt*4+3], L2E, base3 + mv.y + t3.y)));
            l0 += p0[nt*4+0] + p0[nt*4+1];
            l1 += p0[nt*4+2] + p0[nt*4+3];
            l2 += p1[nt*4+0] + p1[nt*4+1];
            l3 += p1[nt*4+2] + p1[nt*4+3];
        }
        // A fragments = accumulator registers, sigma-permuted (pure renaming)
        uint32_t pa0[16], pa1[16];
#pragma unroll
        for (int kt = 0; kt < 4; kt++) {
            pa0[kt*4+0] = U(p0[kt*4+0]);
            pa0[kt*4+1] = U(p0[kt*4+2]);
            pa0[kt*4+2] = U(p0[kt*4+1]);
            pa0[kt*4+3] = U(p0[kt*4+3]);
            pa1[kt*4+0] = U(p1[kt*4+0]);
            pa1[kt*4+1] = U(p1[kt*4+2]);
            pa1[kt*4+2] = U(p1[kt*4+1]);
            pa1[kt*4+3] = U(p1[kt*4+3]);
        }

        // ---- MMA2: O += P X, B shared across both m-tiles ----
#pragma unroll
        for (int nt = 0; nt < 4; nt++) {
            float4 ba  = xt4[(nt*8 + g) * 65 + (kb >> 5) * 8 + tc * 2];
            float4 bb2 = xt4[(nt*8 + g) * 65 + (kb >> 5) * 8 + tc * 2 + 1];
            mma8(&o0[nt*4], &pa0[0],  U(ba.x),  U(ba.y));
            mma8(&o0[nt*4], &pa0[4],  U(ba.z),  U(ba.w));
            mma8(&o0[nt*4], &pa0[8],  U(bb2.x), U(bb2.y));
            mma8(&o0[nt*4], &pa0[12], U(bb2.z), U(bb2.w));
            mma8(&o1[nt*4], &pa1[0],  U(ba.x),  U(ba.y));
            mma8(&o1[nt*4], &pa1[4],  U(ba.z),  U(ba.w));
            mma8(&o1[nt*4], &pa1[8],  U(bb2.x), U(bb2.y));
            mma8(&o1[nt*4], &pa1[12], U(bb2.z), U(bb2.w));
        }
    }

    // ===== epilogue: F = (O Wv^T)/l + bv, A = O regs (sigma), 3xTF32 =====
    float f0[16], f1[16];
#pragma unroll
    for (int q = 0; q < 16; q++) { f0[q] = 0.f; f1[q] = 0.f; }
#pragma unroll
    for (int kt = 0; kt < 4; kt++) {
        float v00 = o0[kt*4+0], v01 = o0[kt*4+2], v02 = o0[kt*4+1], v03 = o0[kt*4+3];
        float v10 = o1[kt*4+0], v11 = o1[kt*4+2], v12 = o1[kt*4+1], v13 = o1[kt*4+3];
        uint32_t oh0[4] = {U(hif(v00)), U(hif(v01)), U(hif(v02)), U(hif(v03))};
        uint32_t ol0[4] = {U(lof(v00, hif(v00))), U(lof(v01, hif(v01))),
                           U(lof(v02, hif(v02))), U(lof(v03, hif(v03)))};
        uint32_t oh1[4] = {U(hif(v10)), U(hif(v11)), U(hif(v12)), U(hif(v13))};
        uint32_t ol1[4] = {U(lof(v10, hif(v10))), U(lof(v11, hif(v11))),
                           U(lof(v12, hif(v12))), U(lof(v13, hif(v13)))};
#pragma unroll
        for (int nt = 0; nt < 4; nt++) {
            float2 bh = *reinterpret_cast<const float2*>(&Wvh[(nt*8 + g) * 36 + kt*8 + 2*tc]);
            float2 bl = *reinterpret_cast<const float2*>(&Wvl[(nt*8 + g) * 36 + kt*8 + 2*tc]);
            mma8(&f0[nt*4], oh0, U(bh.x), U(bh.y));
            mma8(&f0[nt*4], oh0, U(bl.x), U(bl.y));
            mma8(&f0[nt*4], ol0, U(bh.x), U(bh.y));
            mma8(&f1[nt*4], oh1, U(bh.x), U(bh.y));
            mma8(&f1[nt*4], oh1, U(bl.x), U(bl.y));
            mma8(&f1[nt*4], ol1, U(bh.x), U(bh.y));
        }
    }

    l0 += __shfl_xor_sync(0xFFFFFFFFu, l0, 1); l0 += __shfl_xor_sync(0xFFFFFFFFu, l0, 2);
    l1 += __shfl_xor_sync(0xFFFFFFFFu, l1, 1); l1 += __shfl_xor_sync(0xFFFFFFFFu, l1, 2);
    l2 += __shfl_xor_sync(0xFFFFFFFFu, l2, 1); l2 += __shfl_xor_sync(0xFFFFFFFFu, l2, 2);
    l3 += __shfl_xor_sync(0xFFFFFFFFu, l3, 1); l3 += __shfl_xor_sync(0xFFFFFFFFu, l3, 2);
    float inv0 = 1.f / l0, inv1 = 1.f / l1, inv2 = 1.f / l2, inv3 = 1.f / l3;

#pragma unroll
    for (int nt = 0; nt < 4; nt++) {
        int c0 = nt * 8 + 2 * tc;
        float2 bb2 = *reinterpret_cast<const float2*>(&bvs[c0]);
        float2 v0 = make_float2(f0[nt*4+0] * inv0 + bb2.x, f0[nt*4+1] * inv0 + bb2.y);
        float2 v1 = make_float2(f0[nt*4+2] * inv1 + bb2.x, f0[nt*4+3] * inv1 + bb2.y);
        float2 v2 = make_float2(f1[nt*4+0] * inv2 + bb2.x, f1[nt*4+1] * inv2 + bb2.y);
        float2 v3 = make_float2(f1[nt*4+2] * inv3 + bb2.x, f1[nt*4+3] * inv3 + bb2.y);
        *reinterpret_cast<float2*>(out + (((size_t)i * NN + R + g     ) * HH + h) * DD + c0) = v0;
        *reinterpret_cast<float2*>(out + (((size_t)i * NN + R + g + 8 ) * HH + h) * DD + c0) = v1;
        *reinterpret_cast<float2*>(out + (((size_t)i * NN + R + g + 16) * HH + h) * DD + c0) = v2;
        *reinterpret_cast<float2*>(out + (((size_t)i * NN + R + g + 24) * HH + h) * DD + c0) = v3;
    }
}

// ---------------------------------------------------------------------------
extern "C" void kernel_launch(void* const* d_in, const int* in_sizes, int n_in,
                              void* d_out, int out_size) {
    const float* x    = (const float*)d_in[0];
    const float* mask = (const float*)d_in[1];
    const float* Wq   = (const float*)d_in[2];
    const float* bq   = (const float*)d_in[3];
    const float* Wk   = (const float*)d_in[4];
    const float* bk   = (const float*)d_in[5];
    const float* Wv   = (const float*)d_in[6];
    const float* bv   = (const float*)d_in[7];
    const float* Wb   = (const float*)d_in[8];
    const float* bb   = (const float*)d_in[9];
    float* out = (float*)d_out;

    cudaFuncSetAttribute(attn_kernel, cudaFuncAttributeMaxDynamicSharedMemorySize, DYN_BYTES);

    prep_trib_kernel<<<NN + HH, 256>>>(x, Wb, bb, Wq, bq, Wk, bk);
    attn_kernel<<<dim3(NN, HH), 256, DYN_BYTES>>>(x, mask, Wv, bv, out);
}